// round 16
// baseline (speedup 1.0000x reference)
#include <cuda_runtime.h>
#include <cuda_bf16.h>

#define BATCH  64
#define NPTS   1024
#define CHUNKS 16
#define JCH    (NPTS / CHUNKS)      // 64 j per block
#define NQ     (JCH / 4)            // 16 j-quads
#define TPB    256                  // thread t owns shifts t, t+256, t+512, t+768
#define RQUADS 272                  // quads per replica (window N + JCH + pad, /4)
// Replica quad offsets: Q_r mod 8 = {0,3,5,7} -> conflict-free 8-lane phases.
#define Q0 0
#define Q1 275
#define Q2 549
#define Q3 823
#define TOTQ 1095                   // Q3 + RQUADS
#define CSTR (2 * TOTQ)             // u64 stride between x and y planes

// Deterministic scratch (no device-side allocation; zero-initialized globals).
__device__ float g_partial[CHUNKS][BATCH][NPTS];  // 4 MB
__device__ float g_min[BATCH];
__device__ int   g_cnt_b[BATCH];
__device__ int   g_cnt_all;

typedef unsigned long long u64;

__device__ __forceinline__ void upk2(u64 v, float& a, float& b) {
    asm("mov.b64 {%0, %1}, %2;" : "=f"(a), "=f"(b) : "l"(v));
}
__device__ __forceinline__ u64 pk2(float a, float b) {          // fill only
    u64 r; asm("mov.b64 %0, {%1, %2};" : "=l"(r) : "f"(a), "f"(b)); return r;
}
__device__ __forceinline__ u64 addx2(u64 a, u64 b) {
    u64 r; asm("add.rn.f32x2 %0, %1, %2;" : "=l"(r) : "l"(a), "l"(b)); return r;
}
__device__ __forceinline__ u64 mulx2(u64 a, u64 b) {
    u64 r; asm("mul.rn.f32x2 %0, %1, %2;" : "=l"(r) : "l"(a), "l"(b)); return r;
}
__device__ __forceinline__ u64 fmx2(u64 a, u64 b, u64 c) {
    u64 r; asm("fma.rn.f32x2 %0, %1, %2, %3;" : "=l"(r) : "l"(a), "l"(b), "l"(c)); return r;
}
__device__ __forceinline__ float sqrtapx(float x) {
    float r; asm("sqrt.approx.f32 %0, %1;" : "=f"(r) : "f"(x)); return r;
}

// One shift x one j-quad = 4 distances: 2 LDS.128 + packed math, zero packs.
#define QUAD_ACC(ACC, MOFF)                                             \
    {                                                                   \
        ulonglong2 tx = *(const ulonglong2*)(TQ + 2 * (MOFF));          \
        ulonglong2 ty = *(const ulonglong2*)(TQ + CSTR + 2 * (MOFF));   \
        u64 dx0 = addx2(xq0, tx.x), dx1 = addx2(xq1, tx.y);             \
        u64 dy0 = addx2(yq0, ty.x), dy1 = addx2(yq1, ty.y);             \
        u64 d20 = fmx2(dy0, dy0, mulx2(dx0, dx0));                      \
        u64 d21 = fmx2(dy1, dy1, mulx2(dx1, dx1));                      \
        float l0, h0, l1, h1; upk2(d20, l0, h0); upk2(d21, l1, h1);     \
        ACC += sqrtapx(l0); ACC += sqrtapx(h0);                         \
        ACC += sqrtapx(l1); ACC += sqrtapx(h1);                         \
    }

// ---------------------------------------------------------------------------
// Single fused kernel. Grid (CHUNKS, BATCH), TPB=256.
// Negated target stored as 4 residue replicas of 16B quads per coordinate:
//   replica r, quad m = (-T[(j0+4m+r)%N], ..., -T[(j0+4m+r+3)%N])
// Thread t (shifts t+256k) always needs residue r=(-t)&3, quad
//   m = 256 + q - 64k - (t+r)/4, so every target fetch is ONE LDS.128.
// Replica placement Q_r mod 8 = {0,3,5,7} makes each 8-lane phase hit all
// 8 bank-groups exactly once (enumerated) -> conflict-free.
// ---------------------------------------------------------------------------
__global__ void __launch_bounds__(TPB, 5)
snake_kernel(const float2* __restrict__ x, const float2* __restrict__ tg,
             float* __restrict__ out)
{
    __shared__ __align__(16) u64 SMT[2 * CSTR];   // x plane | y plane, 35 KB
    __shared__ __align__(16) u64 XQ[2][2 * NQ];   // x-point quads (x | y)
    __shared__ float redmin[8];
    __shared__ int lastflag;

    const int b     = blockIdx.y;
    const int chunk = blockIdx.x;
    const int j0    = chunk * JCH;
    const int t     = threadIdx.x;

    const float2* __restrict__ tb = tg + b * NPTS;
    const float2* __restrict__ xb = x  + b * NPTS;

    // Fill replicas: 4 * RQUADS = 1088 quads, each = 4 target points.
    {
        const int qoff[4] = {Q0, Q1, Q2, Q3};
        for (int i = t; i < 4 * RQUADS; i += TPB) {
            int r = i / RQUADS;
            int m = i - r * RQUADS;
            int pbase = j0 + 4 * m + r;
            float2 v0 = tb[(pbase    ) & (NPTS - 1)];
            float2 v1 = tb[(pbase + 1) & (NPTS - 1)];
            float2 v2 = tb[(pbase + 2) & (NPTS - 1)];
            float2 v3 = tb[(pbase + 3) & (NPTS - 1)];
            int qp = qoff[r] + m;
            *(ulonglong2*)(SMT + 2 * qp) =
                make_ulonglong2(pk2(-v0.x, -v1.x), pk2(-v2.x, -v3.x));
            *(ulonglong2*)(SMT + CSTR + 2 * qp) =
                make_ulonglong2(pk2(-v0.y, -v1.y), pk2(-v2.y, -v3.y));
        }
    }
    // Fill x-point quads.
    if (t < NQ) {
        float4 fa = ((const float4*)(xb + j0))[2 * t];      // points 4t, 4t+1
        float4 fb = ((const float4*)(xb + j0))[2 * t + 1];  // points 4t+2, 4t+3
        XQ[0][2 * t]     = pk2(fa.x, fa.z);
        XQ[0][2 * t + 1] = pk2(fb.x, fb.z);
        XQ[1][2 * t]     = pk2(fa.y, fa.w);
        XQ[1][2 * t + 1] = pk2(fb.y, fb.w);
    }
    __syncthreads();

    const int r  = (-t) & 3;                   // residue owned by this thread
    const int u  = (t + r) >> 2;
    const int Qr = (r == 0) ? Q0 : (r == 1) ? Q1 : (r == 2) ? Q2 : Q3;
    // Base quad pointer: quad index Qr + (256 - u); per (q,k) offset q - 64k.
    const u64* __restrict__ TQ = SMT + 2 * (Qr + 256 - u);

    float acc0 = 0.0f, acc1 = 0.0f, acc2 = 0.0f, acc3 = 0.0f;

    #pragma unroll
    for (int q = 0; q < NQ; ++q) {
        u64 xq0 = XQ[0][2 * q], xq1 = XQ[0][2 * q + 1];   // broadcast LDS.128
        u64 yq0 = XQ[1][2 * q], yq1 = XQ[1][2 * q + 1];

        QUAD_ACC(acc0, q      )   // k=0: shift t
        QUAD_ACC(acc1, q -  64)   // k=1: shift t+256
        QUAD_ACC(acc2, q - 128)   // k=2: shift t+512
        QUAD_ACC(acc3, q - 192)   // k=3: shift t+768
    }

    g_partial[chunk][b][t]       = acc0;       // coalesced
    g_partial[chunk][b][t + 256] = acc1;
    g_partial[chunk][b][t + 512] = acc2;
    g_partial[chunk][b][t + 768] = acc3;

    // ---- last block of this batch reduces it --------------------------------
    __threadfence();
    if (t == 0) {
        int old = atomicAdd(&g_cnt_b[b], 1);
        lastflag = (old == CHUNKS - 1);
    }
    __syncthreads();
    if (!lastflag) return;
    __threadfence();
    if (t == 0) g_cnt_b[b] = 0;                // reset for next replay

    float mn = 3.4e38f;
    #pragma unroll
    for (int k = 0; k < 4; ++k) {
        int s = t + k * TPB;
        float sum = 0.0f;
        #pragma unroll
        for (int c = 0; c < CHUNKS; ++c)
            sum += __ldcg(&g_partial[c][b][s]);
        mn = fminf(mn, sum);
    }
    #pragma unroll
    for (int o = 16; o > 0; o >>= 1)
        mn = fminf(mn, __shfl_xor_sync(0xFFFFFFFFu, mn, o));
    if ((t & 31) == 0) redmin[t >> 5] = mn;
    __syncthreads();

    if (t == 0) {
        float v = redmin[0];
        #pragma unroll
        for (int w = 1; w < 8; ++w) v = fminf(v, redmin[w]);
        g_min[b] = v;
        __threadfence();
        int old = atomicAdd(&g_cnt_all, 1);
        if (old == BATCH - 1) {                // last batch-reducer
            g_cnt_all = 0;                     // reset for next replay
            float s = 0.0f;
            #pragma unroll
            for (int bb = 0; bb < BATCH; ++bb)
                s += __ldcg(&g_min[bb]);
            out[0] = s * (1.0f / (float)(BATCH * NPTS));
        }
    }
}

// ---------------------------------------------------------------------------
extern "C" void kernel_launch(void* const* d_in, const int* in_sizes, int n_in,
                              void* d_out, int out_size)
{
    const float2* x  = (const float2*)d_in[0];
    const float2* tg = (const float2*)d_in[1];
    float* out = (float*)d_out;

    dim3 grid(CHUNKS, BATCH);
    snake_kernel<<<grid, TPB>>>(x, tg, out);
}

// round 17
// speedup vs baseline: 1.5624x; 1.5624x over previous
#include <cuda_runtime.h>
#include <cuda_bf16.h>

#define BATCH  64
#define NPTS   1024
#define CHUNKS 16
#define JCHUNK (NPTS / CHUNKS)   // 64 j-values per block
#define TPB    256               // threads per block; each owns 4 shifts
#define SPT    4                 // shifts per thread (TPB*SPT == NPTS)

// Deterministic scratch (no device-side allocation; zero-initialized globals).
__device__ float g_partial[CHUNKS][BATCH][NPTS];  // 4 MB
__device__ float g_min[BATCH];
__device__ int   g_cnt_b[BATCH];
__device__ int   g_cnt_all;

typedef unsigned long long u64;

// ---- packed f32x2 helpers (verbatim from the 22.9us R4 kernel) --------------
__device__ __forceinline__ u64 pk2(float a, float b) {
    u64 r; asm("mov.b64 %0, {%1, %2};" : "=l"(r) : "f"(a), "f"(b)); return r;
}
__device__ __forceinline__ void upk2(u64 v, float& a, float& b) {
    asm("mov.b64 {%0, %1}, %2;" : "=f"(a), "=f"(b) : "l"(v));
}
__device__ __forceinline__ u64 addx2(u64 a, u64 b) {
    u64 r; asm("add.rn.f32x2 %0, %1, %2;" : "=l"(r) : "l"(a), "l"(b)); return r;
}
__device__ __forceinline__ u64 mulx2(u64 a, u64 b) {
    u64 r; asm("mul.rn.f32x2 %0, %1, %2;" : "=l"(r) : "l"(a), "l"(b)); return r;
}
__device__ __forceinline__ float sqrt_approx(float x) {
    float r; asm("sqrt.approx.f32 %0, %1;" : "=f"(r) : "f"(x)); return r;
}

// ---------------------------------------------------------------------------
// Single fused kernel. Grid (CHUNKS, BATCH), TPB=256.
// HOT LOOP IS THE MEASURED-BEST R4 KERNEL, UNCHANGED:
//   thread t owns shifts t, t+256, t+512, t+768;
//   target duplicated (2N, negated) in smem -> mod becomes linear index;
//   per j-pair: LDS.128 broadcast of x, 4x2 LDS.64 of target, packed f32x2
//   diff/square, scalar sqrt.approx, packed accumulate.
// After the store, the last block of each batch (atomic counter) sums the
// 16 chunk partials per shift, takes the min over 1024 shifts, and the last
// batch-reducer writes mean(min)/N. All reductions fixed-order/deterministic.
// ---------------------------------------------------------------------------
__global__ void __launch_bounds__(TPB, 6)
snake_kernel(const float2* __restrict__ x, const float2* __restrict__ tg,
             float* __restrict__ out)
{
    __shared__ u64 tdup[2 * NPTS];        // 16 KB, holds (-tx, -ty)
    __shared__ float4 xs4[JCHUNK / 2];    // 512 B, x points in pairs
    __shared__ float redmin[8];
    __shared__ int lastflag;

    const int b     = blockIdx.y;
    const int chunk = blockIdx.x;
    const int j0    = chunk * JCHUNK;
    const int t     = threadIdx.x;

    const float2* __restrict__ tb = tg + b * NPTS;
    const float2* __restrict__ xb = x  + b * NPTS;

    // Fill duplicated negated target (4 points/thread) and x chunk pairs.
    #pragma unroll
    for (int i = t; i < NPTS; i += TPB) {
        float2 tv = tb[i];
        u64 p = pk2(-tv.x, -tv.y);
        tdup[i]        = p;
        tdup[i + NPTS] = p;
    }
    if (t < JCHUNK / 2)
        xs4[t] = *(const float4*)(xb + j0 + 2 * t);
    __syncthreads();

    // tv index for shift s at offset jj: j0 + jj + NPTS - s  (always in [1, 2N-1])
    int base0 = j0 + NPTS - t;
    u64 acc0 = 0, acc1 = 0, acc2 = 0, acc3 = 0;

    #pragma unroll 4
    for (int jj = 0; jj < JCHUNK; jj += 2) {
        float4 xq = xs4[jj >> 1];                    // LDS.128 broadcast: 2 points
        u64 xv0 = pk2(xq.x, xq.y);
        u64 xv1 = pk2(xq.z, xq.w);

        #pragma unroll
        for (int k = 0; k < SPT; ++k) {
            const int bs = base0 - k * TPB + jj;     // shift s = t + k*256
            u64 t0 = tdup[bs];                       // LDS.64, coalesced
            u64 t1 = tdup[bs + 1];

            u64 d0 = addx2(xv0, t0);                 // (dx,dy) in one op
            u64 d1 = addx2(xv1, t1);
            u64 q0 = mulx2(d0, d0);                  // (dx^2,dy^2)
            u64 q1 = mulx2(d1, d1);

            float a0, b0f, a1, b1f;
            upk2(q0, a0, b0f);
            upk2(q1, a1, b1f);
            float r0 = sqrt_approx(a0 + b0f);
            float r1 = sqrt_approx(a1 + b1f);

            u64 dpair = pk2(r0, r1);
            switch (k) {                             // packed accumulate
                case 0: acc0 = addx2(acc0, dpair); break;
                case 1: acc1 = addx2(acc1, dpair); break;
                case 2: acc2 = addx2(acc2, dpair); break;
                case 3: acc3 = addx2(acc3, dpair); break;
            }
        }
    }

    {
        float lo, hi;
        upk2(acc0, lo, hi); g_partial[chunk][b][t          ] = lo + hi;
        upk2(acc1, lo, hi); g_partial[chunk][b][t + TPB    ] = lo + hi;
        upk2(acc2, lo, hi); g_partial[chunk][b][t + 2 * TPB] = lo + hi;
        upk2(acc3, lo, hi); g_partial[chunk][b][t + 3 * TPB] = lo + hi;
    }

    // ---- last block of this batch reduces it --------------------------------
    __threadfence();
    if (t == 0) {
        int old = atomicAdd(&g_cnt_b[b], 1);
        lastflag = (old == CHUNKS - 1);
    }
    __syncthreads();
    if (!lastflag) return;
    __threadfence();
    if (t == 0) g_cnt_b[b] = 0;                      // reset for next replay

    float mn = 3.4e38f;
    #pragma unroll
    for (int k = 0; k < SPT; ++k) {
        int s = t + k * TPB;
        float sum = 0.0f;
        #pragma unroll
        for (int c = 0; c < CHUNKS; ++c)
            sum += __ldcg(&g_partial[c][b][s]);
        mn = fminf(mn, sum);
    }
    #pragma unroll
    for (int o = 16; o > 0; o >>= 1)
        mn = fminf(mn, __shfl_xor_sync(0xFFFFFFFFu, mn, o));
    if ((t & 31) == 0) redmin[t >> 5] = mn;
    __syncthreads();

    if (t == 0) {
        float v = redmin[0];
        #pragma unroll
        for (int w = 1; w < 8; ++w) v = fminf(v, redmin[w]);
        g_min[b] = v;                                // min of raw sums; /N below
        __threadfence();
        int old = atomicAdd(&g_cnt_all, 1);
        if (old == BATCH - 1) {                      // last batch-reducer
            g_cnt_all = 0;                           // reset for next replay
            float s = 0.0f;
            #pragma unroll
            for (int bb = 0; bb < BATCH; ++bb)
                s += __ldcg(&g_min[bb]);
            out[0] = s * (1.0f / (float)(BATCH * NPTS));
        }
    }
}

// ---------------------------------------------------------------------------
extern "C" void kernel_launch(void* const* d_in, const int* in_sizes, int n_in,
                              void* d_out, int out_size)
{
    const float2* x  = (const float2*)d_in[0];
    const float2* tg = (const float2*)d_in[1];
    float* out = (float*)d_out;

    dim3 grid(CHUNKS, BATCH);
    snake_kernel<<<grid, TPB>>>(x, tg, out);
}